// round 8
// baseline (speedup 1.0000x reference)
#include <cuda_runtime.h>
#include <cuda_fp16.h>
#include <stdint.h>

#define RES 512
#define PR  514           // padded resolution: 1-texel zero ring
#define CH  32
#define PLANE_PAD_ELEMS (PR * PR * CH)

// Zero-padded (H, W, C) fp16 planes. Texel = 32 halves = 64B.
// Interior texel (y, x) lives at padded coords (y+1, x+1).
__device__ __align__(128) __half g_TP[3][PLANE_PAD_ELEMS];

// ---------------------------------------------------------------------------
// Prep: transpose (C,H,W) fp32 -> padded (H,W,C) fp16, with the border-ring
// zeroing folded into the blockIdx.y==0 blocks (no separate launch).
// grid = (RES, RES/32, 3), block = (32, 8).
// ---------------------------------------------------------------------------
__global__ __launch_bounds__(256) void triplane_prep_kernel(
    const float* __restrict__ t_xy,
    const float* __restrict__ t_yz,
    const float* __restrict__ t_zx)
{
    __shared__ float tile[32][33];   // [channel][x-in-tile]

    const int y  = blockIdx.x;
    const int x0 = blockIdx.y * 32;
    const int p  = blockIdx.z;
    const int tx = threadIdx.x;      // 0..31
    const int ty = threadIdx.y;      // 0..7
    const int tid = ty * 32 + tx;

    const float* src = (p == 0) ? t_xy : (p == 1) ? t_yz : t_zx;
    const float* sp = src + y * RES + x0 + tx;

#pragma unroll
    for (int i = 0; i < 4; ++i) {
        const int c = ty + 8 * i;
        tile[c][tx] = sp[c * (RES * RES)];   // coalesced, MLP=4
    }

    // Border zeroing: 2052 ring texels per plane, spread over the 512
    // blockIdx.y==0 blocks: block y zeroes texels [4y, 4y+4) (+4 extra on the
    // last block). One texel = 4 x 16B segments handled by 4 threads.
    if (blockIdx.y == 0) {
        const int nt = (y == RES - 1) ? 32 : 16;
        if (tid < nt) {
            const int b   = 4 * y + (tid >> 2);   // border texel index < 2052
            const int seg = tid & 3;
            int by, bx;
            if (b < PR)               { by = 0;                  bx = b; }
            else if (b < 2 * PR)      { by = PR - 1;             bx = b - PR; }
            else if (b < 2 * PR + RES){ by = b - 2 * PR + 1;     bx = 0; }
            else                      { by = b - (2*PR + RES) + 1; bx = PR - 1; }
            *(uint4*)(g_TP[p] + ((size_t)by * PR + bx) * CH + seg * 8) =
                make_uint4(0u, 0u, 0u, 0u);
        }
    }
    __syncthreads();

    if (tid < 128) {
        const int xx  = tid >> 2;        // texel within tile (0..31)
        const int seg = tid & 3;         // 16B segment of the 64B texel

        uint4 v;
#pragma unroll
        for (int j = 0; j < 4; ++j) {
            const int c = seg * 8 + 2 * j;
            ((__half2*)&v)[j] = __floats2half2_rn(tile[c][xx], tile[c + 1][xx]);
        }
        *(uint4*)(g_TP[p] + ((size_t)(y + 1) * PR + (x0 + xx + 1)) * CH + seg * 8) = v;
    }
}

// ---------------------------------------------------------------------------
// Packed f32x2 + 256-bit memory helpers.
// ---------------------------------------------------------------------------
__device__ __forceinline__ unsigned long long pack2(float lo, float hi)
{
    unsigned long long r;
    asm("mov.b64 %0, {%1, %2};" : "=l"(r) : "f"(lo), "f"(hi));
    return r;
}
__device__ __forceinline__ void ffma2(unsigned long long& d,
                                      unsigned long long a,
                                      unsigned long long b)
{
    asm("fma.rn.f32x2 %0, %1, %2, %0;" : "+l"(d) : "l"(a), "l"(b));
}
__device__ __forceinline__ void add2(unsigned long long& d, unsigned long long a)
{
    asm("add.rn.f32x2 %0, %0, %1;" : "+l"(d) : "l"(a));
}
__device__ __forceinline__ float2 unpack2(unsigned long long v)
{
    float2 f;
    asm("mov.b64 {%0, %1}, %2;" : "=f"(f.x), "=f"(f.y) : "l"(v));
    return f;
}
// 256-bit load (sm_100+: LDG.E.256). 32B-aligned source required.
__device__ __forceinline__ void ldg256(const __half* p, uint32_t r[8])
{
    asm("ld.global.nc.v8.b32 {%0,%1,%2,%3,%4,%5,%6,%7}, [%8];"
        : "=r"(r[0]), "=r"(r[1]), "=r"(r[2]), "=r"(r[3]),
          "=r"(r[4]), "=r"(r[5]), "=r"(r[6]), "=r"(r[7])
        : "l"(p));
}

// ---------------------------------------------------------------------------
// Sampling: 4 lanes per point. Lane s: xsel = s>>1 (x corner), c16 = s&1
// (16-channel half). The 4 lanes' 32B v8 loads tile the contiguous 128B
// (x0 | x1) span -> one warp LDG.256 per (plane,row) per point, same
// wavefront count as before but ~26% fewer issued instructions per point.
// ---------------------------------------------------------------------------
__global__ __launch_bounds__(256) void triplane_sample_kernel(
    const float* __restrict__ xyz,
    float* __restrict__ out,
    int npts)
{
    const int gtid = blockIdx.x * blockDim.x + threadIdx.x;
    const int pid  = gtid >> 2;
    const int s    = gtid & 3;
    const int c16  = s & 1;
    const int xsel = s >> 1;
    if (pid >= npts) return;

    const float cx = __ldg(xyz + pid * 3 + 0);
    const float cy = __ldg(xyz + pid * 3 + 1);
    const float cz = __ldg(xyz + pid * 3 + 2);

    // f_xy: (X, Y)   f_yz: (Y, Z)   f_zx: (Z, X)
    const float cA[3] = {cx, cy, cz};   // W coordinate
    const float cB[3] = {cy, cz, cx};   // H coordinate

    // lane's offset (halves) within the 128B span: s=0..3 -> 0,16,32,48
    const int lane_off = xsel * CH + c16 * 16;

    unsigned long long acc[8];
#pragma unroll
    for (int j = 0; j < 8; ++j) acc[j] = 0ull;

#pragma unroll
    for (int p = 0; p < 3; ++p) {
        // padded pixel coord = 256*c + 256.5; c in [-1,1) -> [0.5, 512.5),
        // trunc == floor, indices in [0,512], no clamps/masks.
        const float xf = fmaf(cA[p], 256.0f, 256.5f);
        const float yf = fmaf(cB[p], 256.0f, 256.5f);

        const int ixp = (int)xf;
        const int iyp = (int)yf;
        const float wx1 = xf - (float)ixp;
        const float wy1 = yf - (float)iyp;

        const float wxl = xsel ? wx1 : (1.0f - wx1);
        const float w0  = (1.0f - wy1) * wxl;
        const float w1  = wy1 * wxl;
        const unsigned long long w0p = pack2(w0, w0);
        const unsigned long long w1p = pack2(w1, w1);

        const uint32_t idx = (uint32_t)(iyp * PR + ixp) * CH + lane_off;
        const __half* t = g_TP[p] + idx;

        uint32_t r0[8], r1[8];
        ldg256(t, r0);
        ldg256(t + PR * CH, r1);

#pragma unroll
        for (int j = 0; j < 8; ++j) {
            const float2 f0 = __half22float2(*(const __half2*)&r0[j]);
            ffma2(acc[j], pack2(f0.x, f0.y), w0p);
        }
#pragma unroll
        for (int j = 0; j < 8; ++j) {
            const float2 f1 = __half22float2(*(const __half2*)&r1[j]);
            ffma2(acc[j], pack2(f1.x, f1.y), w1p);
        }
    }

    // Combine the two x-corner partial sums (partner lane = s ^ 2).
#pragma unroll
    for (int j = 0; j < 8; ++j) {
        const unsigned long long o = __shfl_xor_sync(0xffffffffu, acc[j], 2);
        add2(acc[j], o);
    }

    // Lane stores 8 of its 16 summed channels: channels c16*16 + xsel*8 + [0,8).
    // Constant-index selects (no local-memory spill), one 256-bit store.
    float sv[8];
#pragma unroll
    for (int j = 0; j < 4; ++j) {
        const float2 f = unpack2(xsel ? acc[4 + j] : acc[j]);
        sv[2 * j]     = f.x;
        sv[2 * j + 1] = f.y;
    }
    float* o = out + (size_t)pid * CH + c16 * 16 + xsel * 8;
    asm volatile("st.global.v8.b32 [%0], {%1,%2,%3,%4,%5,%6,%7,%8};"
        :: "l"(o),
           "r"(__float_as_uint(sv[0])), "r"(__float_as_uint(sv[1])),
           "r"(__float_as_uint(sv[2])), "r"(__float_as_uint(sv[3])),
           "r"(__float_as_uint(sv[4])), "r"(__float_as_uint(sv[5])),
           "r"(__float_as_uint(sv[6])), "r"(__float_as_uint(sv[7]))
        : "memory");
}

// ---------------------------------------------------------------------------
// kernel_launch
// inputs: xyz [N*3], T_xy, T_yz, T_zx [1*32*512*512] fp32 ; output [N*32] fp32
// ---------------------------------------------------------------------------
extern "C" void kernel_launch(void* const* d_in, const int* in_sizes, int n_in,
                              void* d_out, int out_size)
{
    const float* xyz  = (const float*)d_in[0];
    const float* t_xy = (const float*)d_in[1];
    const float* t_yz = (const float*)d_in[2];
    const float* t_zx = (const float*)d_in[3];
    float* out = (float*)d_out;

    const int npts = in_sizes[0] / 3;

    // 1) transpose + fp16 convert + border zeroing, one launch
    dim3 tgrid(RES, RES / 32, 3);
    dim3 tblock(32, 8);
    triplane_prep_kernel<<<tgrid, tblock>>>(t_xy, t_yz, t_zx);

    // 2) sample: 4 threads per point
    const long long total = (long long)npts * 4;
    const int block = 256;
    const int grid = (int)((total + block - 1) / block);
    triplane_sample_kernel<<<grid, block>>>(xyz, out, npts);
}

// round 9
// speedup vs baseline: 1.1934x; 1.1934x over previous
#include <cuda_runtime.h>
#include <cuda_fp16.h>
#include <stdint.h>

#define RES 512
#define PR  514           // padded resolution: 1-texel zero ring
#define CH  32
#define PLANE_PAD_ELEMS (PR * PR * CH)

// Zero-padded (H, W, C) fp16 planes. Texel = 32 halves = 64B.
// Interior texel (y, x) lives at padded coords (y+1, x+1).
__device__ __align__(128) __half g_TP[3][PLANE_PAD_ELEMS];

// ---------------------------------------------------------------------------
// Prep: transpose (C,H,W) fp32 -> padded (H,W,C) fp16, border-ring zeroing
// folded into the blockIdx.y==0 blocks. grid=(RES, RES/32, 3), block=(32,8).
// ---------------------------------------------------------------------------
__global__ __launch_bounds__(256) void triplane_prep_kernel(
    const float* __restrict__ t_xy,
    const float* __restrict__ t_yz,
    const float* __restrict__ t_zx)
{
    __shared__ float tile[32][33];   // [channel][x-in-tile]

    const int y  = blockIdx.x;
    const int x0 = blockIdx.y * 32;
    const int p  = blockIdx.z;
    const int tx = threadIdx.x;      // 0..31
    const int ty = threadIdx.y;      // 0..7
    const int tid = ty * 32 + tx;

    const float* src = (p == 0) ? t_xy : (p == 1) ? t_yz : t_zx;
    const float* sp = src + y * RES + x0 + tx;

#pragma unroll
    for (int i = 0; i < 4; ++i) {
        const int c = ty + 8 * i;
        tile[c][tx] = sp[c * (RES * RES)];   // coalesced, MLP=4
    }

    // Border zeroing: 2052 ring texels/plane spread over the 512 y-blocks.
    if (blockIdx.y == 0) {
        const int nt = (y == RES - 1) ? 32 : 16;
        if (tid < nt) {
            const int b   = 4 * y + (tid >> 2);   // ring texel index < 2052
            const int seg = tid & 3;
            int by, bx;
            if (b < PR)                 { by = 0;                    bx = b; }
            else if (b < 2 * PR)        { by = PR - 1;               bx = b - PR; }
            else if (b < 2 * PR + RES)  { by = b - 2 * PR + 1;       bx = 0; }
            else                        { by = b - (2 * PR + RES) + 1; bx = PR - 1; }
            *(uint4*)(g_TP[p] + ((size_t)by * PR + bx) * CH + seg * 8) =
                make_uint4(0u, 0u, 0u, 0u);
        }
    }
    __syncthreads();

    if (tid < 128) {
        const int xx  = tid >> 2;        // texel within tile (0..31)
        const int seg = tid & 3;         // 16B segment of the 64B texel

        uint4 v;
#pragma unroll
        for (int j = 0; j < 4; ++j) {
            const int c = seg * 8 + 2 * j;
            ((__half2*)&v)[j] = __floats2half2_rn(tile[c][xx], tile[c + 1][xx]);
        }
        *(uint4*)(g_TP[p] + ((size_t)(y + 1) * PR + (x0 + xx + 1)) * CH + seg * 8) = v;
    }
}

// ---------------------------------------------------------------------------
// Sampling: 8 lanes per point (R6 shape: xsel = s>>2 picks x corner,
// chunk = s&3 picks 8 channels). Per (plane,row) one warp uint4-instruction
// covers the contiguous 128B (x0|x1) span. Padded planes -> zero border math.
// Per-plane bilinear partial in fp16 (HMUL2/HFMA2), accumulated in fp32.
// ---------------------------------------------------------------------------
__global__ __launch_bounds__(256) void triplane_sample_kernel(
    const float* __restrict__ xyz,
    float* __restrict__ out,
    int npts)
{
    const int gtid  = blockIdx.x * blockDim.x + threadIdx.x;
    const int pid   = gtid >> 3;
    const int s     = gtid & 7;
    const int chunk = s & 3;
    const int xsel  = s >> 2;

    // Warp-cooperative coord load: the warp's 4 points need 12 floats
    // (one 48B line). Lanes 0..11 load one each; broadcast via shfl.
    const int lane = threadIdx.x & 31;
    const int wbase_pt = (blockIdx.x * blockDim.x + (threadIdx.x & ~31)) >> 3;
    float cv = 0.f;
    {
        const int ci = wbase_pt * 3 + lane;
        if (lane < 12 && ci < npts * 3) cv = __ldg(xyz + ci);
    }
    const int g = s >> 0 ? (lane >> 3) : (lane >> 3);   // point group 0..3
    const float cx = __shfl_sync(0xffffffffu, cv, (lane >> 3) * 3 + 0);
    const float cy = __shfl_sync(0xffffffffu, cv, (lane >> 3) * 3 + 1);
    const float cz = __shfl_sync(0xffffffffu, cv, (lane >> 3) * 3 + 2);
    (void)g;

    if (pid >= npts) return;

    // f_xy: (X, Y)   f_yz: (Y, Z)   f_zx: (Z, X)
    const float cA[3] = {cx, cy, cz};   // W coordinate
    const float cB[3] = {cy, cz, cx};   // H coordinate

    float acc[8];
#pragma unroll
    for (int j = 0; j < 8; ++j) acc[j] = 0.f;

    const int laneoff = chunk * 8;      // this lane's 8-channel offset (halves)

#pragma unroll
    for (int p = 0; p < 3; ++p) {
        // padded pixel coord = 256*c + 256.5; c in [-1,1) -> [0.5, 512.5):
        // floor indices in [0,512], no clamps, no masks.
        const float xf = fmaf(cA[p], 256.0f, 256.5f);
        const float yf = fmaf(cB[p], 256.0f, 256.5f);

        const float x0f = floorf(xf);
        const float y0f = floorf(yf);
        const float wx1 = xf - x0f;
        const float wy1 = yf - y0f;

        const int ixp = (int)x0f;
        const int iyp = (int)y0f;

        const float wxl = xsel ? wx1 : (1.0f - wx1);
        const float w0  = (1.0f - wy1) * wxl;
        const float w1  = wy1 * wxl;
        const __half2 w0h = __float2half2_rn(w0);   // 1x cvt.rn.f16x2.f32
        const __half2 w1h = __float2half2_rn(w1);

        const __half* t = g_TP[p]
                        + (size_t)(iyp * PR + ixp + xsel) * CH + laneoff;
        const uint4 v0 = __ldg((const uint4*)t);
        const uint4 v1 = __ldg((const uint4*)(t + PR * CH));

        const __half2* h0 = (const __half2*)&v0;
        const __half2* h1 = (const __half2*)&v1;
#pragma unroll
        for (int j = 0; j < 4; ++j) {
            // per-plane bilinear partial in fp16: part = v0*w0 + v1*w1
            const __half2 part = __hfma2(h1[j], w1h, __hmul2(h0[j], w0h));
            const float2 f = __half22float2(part);
            acc[2 * j]     += f.x;
            acc[2 * j + 1] += f.y;
        }
    }

    // Combine the two x-corner partial sums (lane s <-> lane s^4, same chunk).
#pragma unroll
    for (int k = 0; k < 8; ++k)
        acc[k] += __shfl_xor_sync(0xffffffffu, acc[k], 4);

    // xsel=0 stores floats 0-3 of the chunk, xsel=1 stores floats 4-7.
    const float4 o = xsel ? make_float4(acc[4], acc[5], acc[6], acc[7])
                          : make_float4(acc[0], acc[1], acc[2], acc[3]);
    *(float4*)(out + (size_t)pid * CH + chunk * 8 + xsel * 4) = o;
}

// ---------------------------------------------------------------------------
// kernel_launch
// inputs: xyz [N*3], T_xy, T_yz, T_zx [1*32*512*512] fp32 ; output [N*32] fp32
// ---------------------------------------------------------------------------
extern "C" void kernel_launch(void* const* d_in, const int* in_sizes, int n_in,
                              void* d_out, int out_size)
{
    const float* xyz  = (const float*)d_in[0];
    const float* t_xy = (const float*)d_in[1];
    const float* t_yz = (const float*)d_in[2];
    const float* t_zx = (const float*)d_in[3];
    float* out = (float*)d_out;

    const int npts = in_sizes[0] / 3;

    // 1) transpose + fp16 convert + border zeroing, one launch
    dim3 tgrid(RES, RES / 32, 3);
    dim3 tblock(32, 8);
    triplane_prep_kernel<<<tgrid, tblock>>>(t_xy, t_yz, t_zx);

    // 2) sample: 8 threads per point
    const long long total = (long long)npts * 8;
    const int block = 256;
    const int grid = (int)((total + block - 1) / block);
    triplane_sample_kernel<<<grid, block>>>(xyz, out, npts);
}

// round 10
// speedup vs baseline: 1.1936x; 1.0002x over previous
#include <cuda_runtime.h>
#include <cuda_fp16.h>
#include <stdint.h>

#define RES 512
#define PR  514           // padded resolution: 1-texel zero ring
#define CH  32
#define PLANE_PAD_ELEMS (PR * PR * CH)

// Zero-padded (H, W, C) fp16 planes. Texel = 32 halves = 64B.
// Interior texel (y, x) lives at padded coords (y+1, x+1).
__device__ __align__(128) __half g_TP[3][PLANE_PAD_ELEMS];

// ---------------------------------------------------------------------------
// Prep: transpose (C,H,W) fp32 -> padded (H,W,C) fp16, border-ring zeroing
// folded into the blockIdx.y==0 blocks. grid=(RES, RES/32, 3), block=(32,8).
// ---------------------------------------------------------------------------
__global__ __launch_bounds__(256) void triplane_prep_kernel(
    const float* __restrict__ t_xy,
    const float* __restrict__ t_yz,
    const float* __restrict__ t_zx)
{
    __shared__ float tile[32][33];   // [channel][x-in-tile]

    const int y  = blockIdx.x;
    const int x0 = blockIdx.y * 32;
    const int p  = blockIdx.z;
    const int tx = threadIdx.x;      // 0..31
    const int ty = threadIdx.y;      // 0..7
    const int tid = ty * 32 + tx;

    const float* src = (p == 0) ? t_xy : (p == 1) ? t_yz : t_zx;
    const float* sp = src + y * RES + x0 + tx;

#pragma unroll
    for (int i = 0; i < 4; ++i) {
        const int c = ty + 8 * i;
        tile[c][tx] = sp[c * (RES * RES)];   // coalesced, MLP=4
    }

    // Border zeroing: 2052 ring texels/plane spread over the 512 y-blocks.
    if (blockIdx.y == 0) {
        const int nt = (y == RES - 1) ? 32 : 16;
        if (tid < nt) {
            const int b   = 4 * y + (tid >> 2);   // ring texel index < 2052
            const int seg = tid & 3;
            int by, bx;
            if (b < PR)                 { by = 0;                    bx = b; }
            else if (b < 2 * PR)        { by = PR - 1;               bx = b - PR; }
            else if (b < 2 * PR + RES)  { by = b - 2 * PR + 1;       bx = 0; }
            else                        { by = b - (2 * PR + RES) + 1; bx = PR - 1; }
            *(uint4*)(g_TP[p] + ((size_t)by * PR + bx) * CH + seg * 8) =
                make_uint4(0u, 0u, 0u, 0u);
        }
    }
    __syncthreads();

    if (tid < 128) {
        const int xx  = tid >> 2;        // texel within tile (0..31)
        const int seg = tid & 3;         // 16B segment of the 64B texel

        uint4 v;
#pragma unroll
        for (int j = 0; j < 4; ++j) {
            const int c = seg * 8 + 2 * j;
            ((__half2*)&v)[j] = __floats2half2_rn(tile[c][xx], tile[c + 1][xx]);
        }
        *(uint4*)(g_TP[p] + ((size_t)(y + 1) * PR + (x0 + xx + 1)) * CH + seg * 8) = v;
    }
}

// ---------------------------------------------------------------------------
// Sampling: 8 lanes per point (xsel = s>>2 picks x corner, chunk = s&3 picks
// 8 channels). Padded planes -> no border math. ALL SIX plane loads are
// issued back-to-back before any math (MLP=6 per warp) to bury L2-hit
// latency; math (fp16 bilinear partial, fp32 accumulate) follows.
// ---------------------------------------------------------------------------
__global__ __launch_bounds__(256) void triplane_sample_kernel(
    const float* __restrict__ xyz,
    float* __restrict__ out,
    int npts)
{
    const int gtid  = blockIdx.x * blockDim.x + threadIdx.x;
    const int pid   = gtid >> 3;
    const int s     = gtid & 7;
    const int chunk = s & 3;
    const int xsel  = s >> 2;

    // Warp-cooperative coord load: warp's 4 points need 12 floats (one line).
    const int lane = threadIdx.x & 31;
    const int wbase_pt = (blockIdx.x * blockDim.x + (threadIdx.x & ~31)) >> 3;
    float cv = 0.f;
    {
        const int ci = wbase_pt * 3 + lane;
        if (lane < 12 && ci < npts * 3) cv = __ldg(xyz + ci);
    }
    const int pg3 = (lane >> 3) * 3;
    const float cx = __shfl_sync(0xffffffffu, cv, pg3 + 0);
    const float cy = __shfl_sync(0xffffffffu, cv, pg3 + 1);
    const float cz = __shfl_sync(0xffffffffu, cv, pg3 + 2);

    if (pid >= npts) return;

    // f_xy: (X, Y)   f_yz: (Y, Z)   f_zx: (Z, X)
    const float cA[3] = {cx, cy, cz};   // W coordinate
    const float cB[3] = {cy, cz, cx};   // H coordinate

    const int laneoff = chunk * 8;      // this lane's 8-channel offset (halves)

    // --- Phase 1: all addresses + packed weights (no loads consumed yet) ---
    uint32_t off[3];
    __half2 w0h[3], w1h[3];
#pragma unroll
    for (int p = 0; p < 3; ++p) {
        // padded pixel coord = 256*c + 256.5; c in [-1,1) -> [0.5, 512.5):
        // floor indices in [0,512], no clamps, no masks.
        const float xf = fmaf(cA[p], 256.0f, 256.5f);
        const float yf = fmaf(cB[p], 256.0f, 256.5f);

        const float x0f = floorf(xf);
        const float y0f = floorf(yf);
        const float wx1 = xf - x0f;
        const float wy1 = yf - y0f;

        const int ixp = (int)x0f;
        const int iyp = (int)y0f;

        const float wxl = xsel ? wx1 : (1.0f - wx1);
        w0h[p] = __float2half2_rn((1.0f - wy1) * wxl);
        w1h[p] = __float2half2_rn(wy1 * wxl);
        off[p] = (uint32_t)(iyp * PR + ixp + xsel) * CH + laneoff;
    }

    // --- Phase 2: six back-to-back loads (MLP=6) ---
    uint4 v0[3], v1[3];
#pragma unroll
    for (int p = 0; p < 3; ++p) {
        const __half* t = g_TP[p] + off[p];
        v0[p] = __ldg((const uint4*)t);
        v1[p] = __ldg((const uint4*)(t + PR * CH));
    }

    // --- Phase 3: math ---
    float acc[8];
#pragma unroll
    for (int j = 0; j < 8; ++j) acc[j] = 0.f;

#pragma unroll
    for (int p = 0; p < 3; ++p) {
        const __half2* h0 = (const __half2*)&v0[p];
        const __half2* h1 = (const __half2*)&v1[p];
#pragma unroll
        for (int j = 0; j < 4; ++j) {
            // per-plane bilinear partial in fp16: part = v0*w0 + v1*w1
            const __half2 part = __hfma2(h1[j], w1h[p], __hmul2(h0[j], w0h[p]));
            const float2 f = __half22float2(part);
            acc[2 * j]     += f.x;
            acc[2 * j + 1] += f.y;
        }
    }

    // Combine the two x-corner partial sums (lane s <-> lane s^4, same chunk).
#pragma unroll
    for (int k = 0; k < 8; ++k)
        acc[k] += __shfl_xor_sync(0xffffffffu, acc[k], 4);

    // xsel=0 stores floats 0-3 of the chunk, xsel=1 stores floats 4-7.
    const float4 o = xsel ? make_float4(acc[4], acc[5], acc[6], acc[7])
                          : make_float4(acc[0], acc[1], acc[2], acc[3]);
    *(float4*)(out + (size_t)pid * CH + chunk * 8 + xsel * 4) = o;
}

// ---------------------------------------------------------------------------
// kernel_launch
// inputs: xyz [N*3], T_xy, T_yz, T_zx [1*32*512*512] fp32 ; output [N*32] fp32
// ---------------------------------------------------------------------------
extern "C" void kernel_launch(void* const* d_in, const int* in_sizes, int n_in,
                              void* d_out, int out_size)
{
    const float* xyz  = (const float*)d_in[0];
    const float* t_xy = (const float*)d_in[1];
    const float* t_yz = (const float*)d_in[2];
    const float* t_zx = (const float*)d_in[3];
    float* out = (float*)d_out;

    const int npts = in_sizes[0] / 3;

    // 1) transpose + fp16 convert + border zeroing, one launch
    dim3 tgrid(RES, RES / 32, 3);
    dim3 tblock(32, 8);
    triplane_prep_kernel<<<tgrid, tblock>>>(t_xy, t_yz, t_zx);

    // 2) sample: 8 threads per point
    const long long total = (long long)npts * 8;
    const int block = 256;
    const int grid = (int)((total + block - 1) / block);
    triplane_sample_kernel<<<grid, block>>>(xyz, out, npts);
}